// round 7
// baseline (speedup 1.0000x reference)
#include <cuda_runtime.h>
#include <cuda_fp16.h>

#define CONSTRAINT_WEIGHT 0.1f
#define CORRECTION_FACTOR 0.1f
#define MAX_NODES 500000

__device__ float  g_loss;
__device__ __align__(16) float4 g_posP[MAX_NODES];      // padded positions {x,y,z,0}
__device__ __align__(8)  uint2  g_scratchH[MAX_NODES];  // {f16x2(xy), f16x2(z,0)}
// NOTE: g_scratchH starts zeroed (static init) and is re-zeroed by merge_kernel
// after reading, so every kernel_launch call sees a zeroed accumulator.

// Kernel 1: pack pos into float4 (4 nodes/thread, fully vectorized), zero loss.
__global__ void prep_kernel(const float4* __restrict__ pos4, int N) {
    int t = blockIdx.x * blockDim.x + threadIdx.x;   // handles nodes 4t..4t+3
    if (t == 0) g_loss = 0.0f;
    int n0 = 4 * t;
    if (n0 + 3 < N) {
        float4 a = pos4[3 * t + 0];   // x0 y0 z0 x1
        float4 b = pos4[3 * t + 1];   // y1 z1 x2 y2
        float4 c = pos4[3 * t + 2];   // z2 x3 y3 z3
        g_posP[n0 + 0] = make_float4(a.x, a.y, a.z, 0.0f);
        g_posP[n0 + 1] = make_float4(a.w, b.x, b.y, 0.0f);
        g_posP[n0 + 2] = make_float4(b.z, b.w, c.x, 0.0f);
        g_posP[n0 + 3] = make_float4(c.y, c.z, c.w, 0.0f);
    } else if (n0 < N) {
        const float* pos = (const float*)pos4;
        for (int n = n0; n < N; n++)
            g_posP[n] = make_float4(pos[3 * n], pos[3 * n + 1], pos[3 * n + 2], 0.0f);
    }
}

__device__ __forceinline__ unsigned h2_bits(float a, float b) {
    __half2 h = __floats2half2_rn(a, b);
    return *reinterpret_cast<unsigned*>(&h);
}

__device__ __forceinline__ void red_add_v2f16x2(uint2* ptr, unsigned a,
                                                unsigned b) {
    asm volatile("red.global.add.noftz.v2.f16x2 [%0], {%1, %2};"
                 :: "l"(ptr), "r"(a), "r"(b)
                 : "memory");
}

// Kernel 2: 2 edges/thread; constraint + fp16x2 scatter-add + loss reduction.
__global__ void __launch_bounds__(512)
edge_kernel(const int* __restrict__ row_idx,
            const int* __restrict__ col_idx,
            const int* __restrict__ bond_types,
            const float* __restrict__ target_lengths,
            const float* __restrict__ length_adjustment,
            int E) {
    __shared__ float s_tgt[5];
    if (threadIdx.x < 5)
        s_tgt[threadIdx.x] = target_lengths[threadIdx.x] + length_adjustment[threadIdx.x];
    __syncthreads();

    int t = blockIdx.x * blockDim.x + threadIdx.x;
    int e0 = 2 * t;
    float err = 0.0f;

    if (e0 + 1 < E) {
        int2 r2 = *(const int2*)&row_idx[e0];
        int2 c2 = *(const int2*)&col_idx[e0];
        int2 b2 = *(const int2*)&bond_types[e0];

        float4 pr0 = __ldg(&g_posP[r2.x]);
        float4 pc0 = __ldg(&g_posP[c2.x]);
        float4 pr1 = __ldg(&g_posP[r2.y]);
        float4 pc1 = __ldg(&g_posP[c2.y]);

        // edge 0
        {
            int b = min(max(b2.x, 0), 4);
            float dx = pr0.x - pc0.x, dy = pr0.y - pc0.y, dz = pr0.z - pc0.z;
            float len = fmaxf(sqrtf(dx * dx + dy * dy + dz * dz), 1e-6f);
            float tgt = s_tgt[b];
            err += fabsf(len - tgt);
            float ratio = fminf(fmaxf(tgt / len, 0.8f), 1.2f);
            float s = (ratio - 1.0f) * (CORRECTION_FACTOR * 0.5f);
            float hx = dx * s, hy = dy * s, hz = dz * s;
            red_add_v2f16x2(&g_scratchH[r2.x], h2_bits(hx, hy),   h2_bits(hz, 0.0f));
            red_add_v2f16x2(&g_scratchH[c2.x], h2_bits(-hx, -hy), h2_bits(-hz, 0.0f));
        }
        // edge 1
        {
            int b = min(max(b2.y, 0), 4);
            float dx = pr1.x - pc1.x, dy = pr1.y - pc1.y, dz = pr1.z - pc1.z;
            float len = fmaxf(sqrtf(dx * dx + dy * dy + dz * dz), 1e-6f);
            float tgt = s_tgt[b];
            err += fabsf(len - tgt);
            float ratio = fminf(fmaxf(tgt / len, 0.8f), 1.2f);
            float s = (ratio - 1.0f) * (CORRECTION_FACTOR * 0.5f);
            float hx = dx * s, hy = dy * s, hz = dz * s;
            red_add_v2f16x2(&g_scratchH[r2.y], h2_bits(hx, hy),   h2_bits(hz, 0.0f));
            red_add_v2f16x2(&g_scratchH[c2.y], h2_bits(-hx, -hy), h2_bits(-hz, 0.0f));
        }
    } else if (e0 < E) {
        int r = row_idx[e0], c = col_idx[e0];
        int b = min(max(bond_types[e0], 0), 4);
        float4 pr = __ldg(&g_posP[r]);
        float4 pc = __ldg(&g_posP[c]);
        float dx = pr.x - pc.x, dy = pr.y - pc.y, dz = pr.z - pc.z;
        float len = fmaxf(sqrtf(dx * dx + dy * dy + dz * dz), 1e-6f);
        float tgt = s_tgt[b];
        err += fabsf(len - tgt);
        float ratio = fminf(fmaxf(tgt / len, 0.8f), 1.2f);
        float s = (ratio - 1.0f) * (CORRECTION_FACTOR * 0.5f);
        float hx = dx * s, hy = dy * s, hz = dz * s;
        red_add_v2f16x2(&g_scratchH[r], h2_bits(hx, hy),   h2_bits(hz, 0.0f));
        red_add_v2f16x2(&g_scratchH[c], h2_bits(-hx, -hy), h2_bits(-hz, 0.0f));
    }

    // Block reduction of err -> one atomic per block.
    __shared__ float warp_sums[16];
    int lane = threadIdx.x & 31;
    int wid = threadIdx.x >> 5;

    #pragma unroll
    for (int off = 16; off > 0; off >>= 1)
        err += __shfl_down_sync(0xFFFFFFFFu, err, off);
    if (lane == 0) warp_sums[wid] = err;
    __syncthreads();
    if (wid == 0) {
        int nw = blockDim.x >> 5;
        float v = (lane < nw) ? warp_sums[lane] : 0.0f;
        #pragma unroll
        for (int off = 8; off > 0; off >>= 1)
            v += __shfl_down_sync(0xFFFFFFFFu, v, off);
        if (lane == 0) atomicAdd(&g_loss, v);
    }
}

// Kernel 3: out = posP + scratch (4 nodes/thread), re-zero scratch, write loss.
__global__ void merge_kernel(float4* __restrict__ out4, int N, int n3,
                             float inv_e) {
    int t = blockIdx.x * blockDim.x + threadIdx.x;
    if (t == 0) ((float*)out4)[n3] = g_loss * inv_e * CONSTRAINT_WEIGHT;
    int n0 = 4 * t;

    if (n0 + 3 < N) {
        float o[12];
        #pragma unroll
        for (int k = 0; k < 4; k++) {
            float4 p = g_posP[n0 + k];
            uint2 sb = g_scratchH[n0 + k];
            g_scratchH[n0 + k] = make_uint2(0u, 0u);  // re-zero for next call
            float2 xy = __half22float2(*reinterpret_cast<__half2*>(&sb.x));
            float2 z_ = __half22float2(*reinterpret_cast<__half2*>(&sb.y));
            o[3 * k + 0] = p.x + xy.x;
            o[3 * k + 1] = p.y + xy.y;
            o[3 * k + 2] = p.z + z_.x;
        }
        out4[3 * t + 0] = make_float4(o[0], o[1], o[2],  o[3]);
        out4[3 * t + 1] = make_float4(o[4], o[5], o[6],  o[7]);
        out4[3 * t + 2] = make_float4(o[8], o[9], o[10], o[11]);
    } else if (n0 < N) {
        float* out = (float*)out4;
        for (int n = n0; n < N; n++) {
            float4 p = g_posP[n];
            uint2 sb = g_scratchH[n];
            g_scratchH[n] = make_uint2(0u, 0u);
            float2 xy = __half22float2(*reinterpret_cast<__half2*>(&sb.x));
            float2 z_ = __half22float2(*reinterpret_cast<__half2*>(&sb.y));
            out[3 * n + 0] = p.x + xy.x;
            out[3 * n + 1] = p.y + xy.y;
            out[3 * n + 2] = p.z + z_.x;
        }
    }
}

extern "C" void kernel_launch(void* const* d_in, const int* in_sizes, int n_in,
                              void* d_out, int out_size) {
    const float* pos = (const float*)d_in[0];
    const int*   edge_index = (const int*)d_in[1];   // JAX x64 disabled -> int32
    const int*   bond_types = (const int*)d_in[2];
    const float* target_lengths = (const float*)d_in[3];
    const float* length_adjustment = (const float*)d_in[4];
    float* out = (float*)d_out;

    const int E = in_sizes[2];
    const int n3 = out_size - 1;   // 3 * N_NODES
    const int N = n3 / 3;

    const int* row_idx = edge_index;
    const int* col_idx = edge_index + E;

    int prep_threads = (N + 3) / 4;
    prep_kernel<<<(prep_threads + 255) / 256, 256>>>((const float4*)pos, N);

    int edge_threads = (E + 1) / 2;
    edge_kernel<<<(edge_threads + 511) / 512, 512>>>(
        row_idx, col_idx, bond_types, target_lengths, length_adjustment, E);

    merge_kernel<<<(prep_threads + 255) / 256, 256>>>(
        (float4*)out, N, n3, 1.0f / (float)E);
}

// round 8
// speedup vs baseline: 1.0182x; 1.0182x over previous
#include <cuda_runtime.h>
#include <cuda_fp16.h>

#define CONSTRAINT_WEIGHT 0.1f
#define CORRECTION_FACTOR 0.1f
#define MAX_NODES 500000

__device__ float  g_loss;
__device__ __align__(16) float4 g_posP[MAX_NODES];      // padded positions {x,y,z,0}
__device__ __align__(8)  uint2  g_scratchH[MAX_NODES];  // {f16x2(xy), f16x2(z,0)}

// Kernel 1: pack pos into float4, zero scratch + loss.
__global__ void prep_kernel(const float* __restrict__ pos, int N) {
    int n = blockIdx.x * blockDim.x + threadIdx.x;
    if (n == 0) g_loss = 0.0f;
    if (n < N) {
        float x = pos[3 * n + 0];
        float y = pos[3 * n + 1];
        float z = pos[3 * n + 2];
        g_posP[n] = make_float4(x, y, z, 0.0f);
        g_scratchH[n] = make_uint2(0u, 0u);
    }
}

__device__ __forceinline__ unsigned h2_bits(float a, float b) {
    __half2 h = __floats2half2_rn(a, b);
    return *reinterpret_cast<unsigned*>(&h);
}

__device__ __forceinline__ void red_add_v2f16x2(uint2* ptr, unsigned a,
                                                unsigned b) {
    asm volatile("red.global.add.noftz.v2.f16x2 [%0], {%1, %2};"
                 :: "l"(ptr), "r"(a), "r"(b)
                 : "memory");
}

// Kernel 2: per-edge constraint + fp16x2 scatter-add + loss reduction.
__global__ void __launch_bounds__(512)
edge_kernel(const int* __restrict__ row_idx,
            const int* __restrict__ col_idx,
            const int* __restrict__ bond_types,
            const float* __restrict__ target_lengths,
            const float* __restrict__ length_adjustment,
            int E) {
    __shared__ float s_tgt[5];
    if (threadIdx.x < 5)
        s_tgt[threadIdx.x] = target_lengths[threadIdx.x] + length_adjustment[threadIdx.x];
    __syncthreads();

    int e = blockIdx.x * blockDim.x + threadIdx.x;
    float err = 0.0f;

    if (e < E) {
        int r = row_idx[e];
        int c = col_idx[e];
        int b = bond_types[e];
        b = min(max(b, 0), 4);

        float4 pr = __ldg(&g_posP[r]);
        float4 pc = __ldg(&g_posP[c]);

        float dx = pr.x - pc.x;
        float dy = pr.y - pc.y;
        float dz = pr.z - pc.z;

        float len = fmaxf(sqrtf(dx * dx + dy * dy + dz * dz), 1e-6f);

        float tgt = s_tgt[b];
        err = fabsf(len - tgt);

        float ratio = fminf(fmaxf(tgt / len, 0.8f), 1.2f);
        float s = (ratio - 1.0f) * (CORRECTION_FACTOR * 0.5f);

        float hx = dx * s, hy = dy * s, hz = dz * s;

        red_add_v2f16x2(&g_scratchH[r], h2_bits(hx, hy),   h2_bits(hz, 0.0f));
        red_add_v2f16x2(&g_scratchH[c], h2_bits(-hx, -hy), h2_bits(-hz, 0.0f));
    }

    // Block reduction of err -> one atomic per block.
    __shared__ float warp_sums[16];
    int lane = threadIdx.x & 31;
    int wid = threadIdx.x >> 5;

    #pragma unroll
    for (int off = 16; off > 0; off >>= 1)
        err += __shfl_down_sync(0xFFFFFFFFu, err, off);
    if (lane == 0) warp_sums[wid] = err;
    __syncthreads();
    if (wid == 0) {
        int nw = blockDim.x >> 5;
        float v = (lane < nw) ? warp_sums[lane] : 0.0f;
        #pragma unroll
        for (int off = 8; off > 0; off >>= 1)
            v += __shfl_down_sync(0xFFFFFFFFu, v, off);
        if (lane == 0) atomicAdd(&g_loss, v);
    }
}

// Kernel 3: out = posP + scratch (coalesced), write loss scalar.
__global__ void merge_kernel(float* __restrict__ out, int N, int n3,
                             float inv_e) {
    int n = blockIdx.x * blockDim.x + threadIdx.x;
    if (n == 0) out[n3] = g_loss * inv_e * CONSTRAINT_WEIGHT;
    if (n < N) {
        float4 p = g_posP[n];
        uint2 sb = g_scratchH[n];
        float2 xy = __half22float2(*reinterpret_cast<__half2*>(&sb.x));
        float2 z_ = __half22float2(*reinterpret_cast<__half2*>(&sb.y));
        out[3 * n + 0] = p.x + xy.x;
        out[3 * n + 1] = p.y + xy.y;
        out[3 * n + 2] = p.z + z_.x;
    }
}

extern "C" void kernel_launch(void* const* d_in, const int* in_sizes, int n_in,
                              void* d_out, int out_size) {
    const float* pos = (const float*)d_in[0];
    const int*   edge_index = (const int*)d_in[1];   // JAX x64 disabled -> int32
    const int*   bond_types = (const int*)d_in[2];
    const float* target_lengths = (const float*)d_in[3];
    const float* length_adjustment = (const float*)d_in[4];
    float* out = (float*)d_out;

    const int E = in_sizes[2];
    const int n3 = out_size - 1;   // 3 * N_NODES
    const int N = n3 / 3;

    const int* row_idx = edge_index;
    const int* col_idx = edge_index + E;

    prep_kernel<<<(N + 255) / 256, 256>>>(pos, N);
    edge_kernel<<<(E + 511) / 512, 512>>>(
        row_idx, col_idx, bond_types, target_lengths, length_adjustment, E);
    merge_kernel<<<(N + 255) / 256, 256>>>(out, N, n3, 1.0f / (float)E);
}

// round 9
// speedup vs baseline: 1.0197x; 1.0014x over previous
#include <cuda_runtime.h>
#include <cuda_fp16.h>

#define CONSTRAINT_WEIGHT 0.1f
#define CORRECTION_FACTOR 0.1f
#define MAX_NODES 500000

__device__ float  g_loss;
__device__ __align__(16) float4 g_posP[MAX_NODES];      // padded positions {x,y,z,0}
__device__ __align__(8)  uint2  g_scratchH[MAX_NODES];  // {f16x2(xy), f16x2(z,0)}

// Kernel 1: pack pos into float4, zero scratch + loss.
__global__ void prep_kernel(const float* __restrict__ pos, int N) {
    int n = blockIdx.x * blockDim.x + threadIdx.x;
    if (n == 0) g_loss = 0.0f;
    if (n < N) {
        float x = pos[3 * n + 0];
        float y = pos[3 * n + 1];
        float z = pos[3 * n + 2];
        g_posP[n] = make_float4(x, y, z, 0.0f);
        g_scratchH[n] = make_uint2(0u, 0u);
    }
}

__device__ __forceinline__ unsigned h2_bits(float a, float b) {
    __half2 h = __floats2half2_rn(a, b);
    return *reinterpret_cast<unsigned*>(&h);
}

__device__ __forceinline__ void red_add_v2f16x2(uint2* ptr, unsigned a,
                                                unsigned b) {
    asm volatile("red.global.add.noftz.v2.f16x2 [%0], {%1, %2};"
                 :: "l"(ptr), "r"(a), "r"(b)
                 : "memory");
}

// Kernel 2: per-edge constraint + fp16x2 scatter-add + loss reduction.
__global__ void __launch_bounds__(512)
edge_kernel(const int* __restrict__ row_idx,
            const int* __restrict__ col_idx,
            const int* __restrict__ bond_types,
            const float* __restrict__ target_lengths,
            const float* __restrict__ length_adjustment,
            int E) {
    int e = blockIdx.x * blockDim.x + threadIdx.x;
    float err = 0.0f;

    if (e < E) {
        int r = row_idx[e];
        int c = col_idx[e];
        int b = bond_types[e];
        b = min(max(b, 0), 4);

        float4 pr = __ldg(&g_posP[r]);
        float4 pc = __ldg(&g_posP[c]);

        float dx = pr.x - pc.x;
        float dy = pr.y - pc.y;
        float dz = pr.z - pc.z;

        float len = fmaxf(sqrtf(dx * dx + dy * dy + dz * dz), 1e-6f);

        float tgt = __ldg(&target_lengths[b]) + __ldg(&length_adjustment[b]);
        err = fabsf(len - tgt);

        float ratio = fminf(fmaxf(tgt / len, 0.8f), 1.2f);
        float s = (ratio - 1.0f) * (CORRECTION_FACTOR * 0.5f);

        float hx = dx * s, hy = dy * s, hz = dz * s;

        red_add_v2f16x2(&g_scratchH[r], h2_bits(hx, hy),   h2_bits(hz, 0.0f));
        red_add_v2f16x2(&g_scratchH[c], h2_bits(-hx, -hy), h2_bits(-hz, 0.0f));
    }

    // Block reduction of err -> one atomic per block.
    __shared__ float warp_sums[16];
    int lane = threadIdx.x & 31;
    int wid = threadIdx.x >> 5;

    #pragma unroll
    for (int off = 16; off > 0; off >>= 1)
        err += __shfl_down_sync(0xFFFFFFFFu, err, off);
    if (lane == 0) warp_sums[wid] = err;
    __syncthreads();
    if (wid == 0) {
        int nw = blockDim.x >> 5;
        float v = (lane < nw) ? warp_sums[lane] : 0.0f;
        #pragma unroll
        for (int off = 8; off > 0; off >>= 1)
            v += __shfl_down_sync(0xFFFFFFFFu, v, off);
        if (lane == 0) atomicAdd(&g_loss, v);
    }
}

// Kernel 3: out = pos + scratch (coalesced), write loss scalar.
__global__ void merge_kernel(const float* __restrict__ pos,
                             float* __restrict__ out, int N, int n3,
                             float inv_e) {
    int n = blockIdx.x * blockDim.x + threadIdx.x;
    if (n == 0) out[n3] = g_loss * inv_e * CONSTRAINT_WEIGHT;
    if (n < N) {
        uint2 sb = g_scratchH[n];
        float2 xy = __half22float2(*reinterpret_cast<__half2*>(&sb.x));
        float2 z_ = __half22float2(*reinterpret_cast<__half2*>(&sb.y));
        out[3 * n + 0] = pos[3 * n + 0] + xy.x;
        out[3 * n + 1] = pos[3 * n + 1] + xy.y;
        out[3 * n + 2] = pos[3 * n + 2] + z_.x;
    }
}

extern "C" void kernel_launch(void* const* d_in, const int* in_sizes, int n_in,
                              void* d_out, int out_size) {
    const float* pos = (const float*)d_in[0];
    const int*   edge_index = (const int*)d_in[1];   // JAX x64 disabled -> int32
    const int*   bond_types = (const int*)d_in[2];
    const float* target_lengths = (const float*)d_in[3];
    const float* length_adjustment = (const float*)d_in[4];
    float* out = (float*)d_out;

    const int E = in_sizes[2];
    const int n3 = out_size - 1;   // 3 * N_NODES
    const int N = n3 / 3;

    const int* row_idx = edge_index;
    const int* col_idx = edge_index + E;

    prep_kernel<<<(N + 255) / 256, 256>>>(pos, N);
    edge_kernel<<<(E + 511) / 512, 512>>>(
        row_idx, col_idx, bond_types, target_lengths, length_adjustment, E);
    merge_kernel<<<(N + 255) / 256, 256>>>(pos, out, N, n3, 1.0f / (float)E);
}